// round 15
// baseline (speedup 1.0000x reference)
#include <cuda_runtime.h>
#include <cuda_fp16.h>
#include <math.h>
#include <stdint.h>

#define S_LEN  2048
#define BSZ    2
#define DMODEL 512
#define NHEADS 8
#define DHEAD  64
#define ZB     (BSZ*NHEADS)          // 16
#define MROWS  (S_LEN*BSZ)           // 4096
#define NWIN   32
#define KSX    512                   // X row: fp16
#define KSW    512                   // W row: fp16
#define NTOT   1024                  // Q,K columns only (V eliminated)
#define KC     64                    // K chunk (fp16) = 128B rows
#define NCHUNK 8
#define STAGES 3
#define ATILE  16384                 // 128 x 64 fp16
#define BTILE  16384
#define STAGE_BYTES (ATILE+BTILE)
#define SMEM_BYTES  (STAGES*STAGE_BYTES)   // 96 KB
#define RCHUNK 16                    // s-chunks per z in reduce_kv

// Kernel-1 block roles
#define XCV_BLOCKS  512              // X convert: 4 float4 / thread
#define WCV_BLOCKS  512              // Wq+Wk convert: 1 float4 / thread
#define FIL_BLOCKS  512              // bias fill of ALL 2048 rows
#define K1_BLOCKS   (XCV_BLOCKS + WCV_BLOCKS + FIL_BLOCKS)   // 1536

// ---------------- static scratch (no cudaMalloc allowed) -------------------
__device__ __align__(16) __half g_Xc[(size_t)MROWS*KSX];  // 4.2 MB
__device__ __align__(16) __half g_Wc[(size_t)NTOT*KSW];   // 1.0 MB
__device__ __align__(16) __half g_Qh[(size_t)ZB*S_LEN*DHEAD];  // fp16 Q
__device__ __align__(16) __half g_Kh[(size_t)ZB*S_LEN*DHEAD];  // fp16 K
__device__ __align__(16) float g_yp[(size_t)ZB*RCHUNK*DMODEL]; // y partials
__device__ float g_Sp[ZB*RCHUNK];                              // S partials
__device__ __align__(16) float g_v2[ZB*DHEAD];
__device__ int   g_cnt[ZB];          // replay-safe via &15
__device__ __align__(16) float g_c[ZB*NWIN];

// ---------------- helpers ---------------------------------------------------
__device__ __forceinline__ uint32_t smem_u32(const void* p) {
    uint32_t a;
    asm("{ .reg .u64 t; cvta.to.shared.u64 t, %1; cvt.u32.u64 %0, t; }"
        : "=r"(a) : "l"(p));
    return a;
}
__device__ __forceinline__ uint32_t swz(uint32_t off) {
    return off ^ ((off >> 3) & 0x70);      // SW128
}
__device__ __forceinline__ void cp16(uint32_t saddr, const void* g) {
    asm volatile("cp.async.cg.shared.global [%0], [%1], 16;"
                 :: "r"(saddr), "l"(g) : "memory");
}
#define CP_COMMIT() asm volatile("cp.async.commit_group;" ::: "memory")
#define CP_WAIT(n)  asm volatile("cp.async.wait_group %0;" :: "n"(n) : "memory")

__device__ __forceinline__ void ldmx4(uint32_t& r0, uint32_t& r1,
                                      uint32_t& r2, uint32_t& r3, uint32_t a) {
    asm volatile("ldmatrix.sync.aligned.m8n8.x4.shared.b16 {%0,%1,%2,%3}, [%4];"
                 : "=r"(r0), "=r"(r1), "=r"(r2), "=r"(r3) : "r"(a));
}
__device__ __forceinline__ void mma16816(float* c, const uint32_t* a,
                                         uint32_t b0, uint32_t b1) {
    asm volatile(
        "mma.sync.aligned.m16n8k16.row.col.f32.f16.f16.f32 "
        "{%0,%1,%2,%3}, {%4,%5,%6,%7}, {%8,%9}, {%0,%1,%2,%3};"
        : "+f"(c[0]), "+f"(c[1]), "+f"(c[2]), "+f"(c[3])
        : "r"(a[0]), "r"(a[1]), "r"(a[2]), "r"(a[3]), "r"(b0), "r"(b1));
}
// Load 16 consecutive halves (32B, 16B-aligned) and widen to float[16].
__device__ __forceinline__ void ld16h(const __half* p, float* f) {
    const uint4 u0 = *(const uint4*)p;
    const uint4 u1 = *(const uint4*)(p + 8);
    const __half2* h0 = (const __half2*)&u0;
    const __half2* h1 = (const __half2*)&u1;
    #pragma unroll
    for (int i = 0; i < 4; i++) {
        const float2 a = __half22float2(h0[i]);
        f[i * 2] = a.x; f[i * 2 + 1] = a.y;
    }
    #pragma unroll
    for (int i = 0; i < 4; i++) {
        const float2 a = __half22float2(h1[i]);
        f[8 + i * 2] = a.x; f[8 + i * 2 + 1] = a.y;
    }
}

// ---------------------------------------------------------------------------
// Kernel A:
//   [0,512)       : X -> fp16, 4 float4/thread
//   [512,1024)    : Wq,Wk -> fp16
//   [1024,1536)   : bias fill of ALL 2048 output rows (atomic base)
// ---------------------------------------------------------------------------
__global__ __launch_bounds__(256) void convert_xw(
    const float* __restrict__ x,
    const float* __restrict__ Wq, const float* __restrict__ Wk,
    float* __restrict__ out, const float* __restrict__ bo)
{
    const int tid = threadIdx.x;
    const int bid = blockIdx.x;
    const int W4PM = DMODEL / 4;                       // 128 float4 per row

    if (bid < XCV_BLOCKS) {
        #pragma unroll
        for (int j = 0; j < 4; j++) {
            const int tid4 = bid * 1024 + j * 256 + tid;
            const float4 v = ((const float4*)x)[tid4];
            const int m    = tid4 / W4PM;
            const int koff = (tid4 % W4PM) * 4;
            __half2 hi01 = __halves2half2(__float2half_rn(v.x), __float2half_rn(v.y));
            __half2 hi23 = __halves2half2(__float2half_rn(v.z), __float2half_rn(v.w));
            __half2* d0 = (__half2*)(g_Xc + (size_t)m * KSX + koff);
            d0[0] = hi01; d0[1] = hi23;
        }
    } else if (bid < XCV_BLOCKS + WCV_BLOCKS) {
        const int wi   = (bid - XCV_BLOCKS) * 256 + tid;
        const int n    = wi / W4PM;                    // 0..1023
        const int koff = (wi % W4PM) * 4;
        const int sel  = n >> 9, row = n & 511;
        const float* W = (sel == 0) ? Wq : Wk;
        const float4 v = *(const float4*)(W + (size_t)row * DMODEL + koff);
        __half2 hi01 = __halves2half2(__float2half_rn(v.x), __float2half_rn(v.y));
        __half2 hi23 = __halves2half2(__float2half_rn(v.z), __float2half_rn(v.w));
        __half2* d0 = (__half2*)(g_Wc + (size_t)n * KSW + koff);
        d0[0] = hi01; d0[1] = hi23;
    } else {
        __shared__ __align__(16) float4 sb[128];
        if (tid < 128) sb[tid] = ((const float4*)bo)[tid];
        __syncthreads();
        const int blk = bid - (XCV_BLOCKS + WCV_BLOCKS);   // 0..511
        float4* out4 = (float4*)out;
        #pragma unroll
        for (int j = 0; j < 4; j++) {
            const int idx = blk * 1024 + j * 256 + tid;
            out4[idx] = sb[idx & 127];
        }
    }
}

// ---------------------------------------------------------------------------
// Kernel B: fp16 warp-MMA GEMM for Q and K only (8 bn blocks).
// ---------------------------------------------------------------------------
__global__ __launch_bounds__(256, 2) void gemm_mma(
    const float* __restrict__ bq, const float* __restrict__ bk,
    const float* __restrict__ beta)
{
    extern __shared__ __align__(1024) char smem[];
    const uint32_t sbase = smem_u32(smem);
    const int tid  = threadIdx.x;
    const int lane = tid & 31;
    const int wid  = tid >> 5;
    const int bn = blockIdx.x;           // 0..7
    const int bm = blockIdx.y;           // 0..31
    const int sel = bn >> 2;             // 0=Q,1=K

    const __half* __restrict__ Xb = g_Xc + (size_t)(bm * 128) * KSX;
    const __half* __restrict__ Wb = g_Wc + (size_t)(bn * 128) * KSW;

    const int r0  = tid >> 3;
    const int c16 = tid & 7;
    uint32_t so[4];
    #pragma unroll
    for (int j = 0; j < 4; j++)
        so[j] = swz((uint32_t)((r0 + 32 * j) * 128 + c16 * 16));

    const int wm = wid & 3;
    const int wn = wid >> 2;
    const int g  = lane >> 2;
    const int t  = lane & 3;

    const int a_row = wm * 32 + (lane & 15);
    const int a_kb  = (lane >> 4) * 16;
    const int b_row = wn * 64 + (lane & 7) + (lane >> 4) * 8;
    const int b_kb  = ((lane >> 3) & 1) * 16;

    float acc[2][8][4];
    #pragma unroll
    for (int i = 0; i < 2; i++)
        #pragma unroll
        for (int j = 0; j < 8; j++)
            #pragma unroll
            for (int q = 0; q < 4; q++) acc[i][j][q] = 0.f;

    #pragma unroll
    for (int s = 0; s < STAGES - 1; s++) {
        uint32_t sA = sbase + s * STAGE_BYTES;
        uint32_t sB = sA + ATILE;
        const __half* gA = Xb + (size_t)s * KC + c16 * 8;
        const __half* gB = Wb + (size_t)s * KC + c16 * 8;
        #pragma unroll
        for (int j = 0; j < 4; j++) {
            cp16(sA + so[j], gA + (size_t)(r0 + 32 * j) * KSX);
            cp16(sB + so[j], gB + (size_t)(r0 + 32 * j) * KSW);
        }
        CP_COMMIT();
    }

    for (int i = 0; i < NCHUNK; i++) {
        CP_WAIT(STAGES - 2);
        __syncthreads();

        const int nxt = i + STAGES - 1;
        if (nxt < NCHUNK) {
            const int st = nxt % STAGES;
            uint32_t sA = sbase + st * STAGE_BYTES;
            uint32_t sB = sA + ATILE;
            const __half* gA = Xb + (size_t)nxt * KC + c16 * 8;
            const __half* gB = Wb + (size_t)nxt * KC + c16 * 8;
            #pragma unroll
            for (int j = 0; j < 4; j++) {
                cp16(sA + so[j], gA + (size_t)(r0 + 32 * j) * KSX);
                cp16(sB + so[j], gB + (size_t)(r0 + 32 * j) * KSW);
            }
        }
        CP_COMMIT();

        const uint32_t sA = sbase + (i % STAGES) * STAGE_BYTES;
        const uint32_t sB = sA + ATILE;
        #pragma unroll
        for (int k16 = 0; k16 < 4; k16++) {
            uint32_t af[2][4];
            #pragma unroll
            for (int mt = 0; mt < 2; mt++) {
                uint32_t addr = sA + swz((uint32_t)((a_row + mt * 16) * 128
                                                    + k16 * 32 + a_kb));
                ldmx4(af[mt][0], af[mt][1], af[mt][2], af[mt][3], addr);
            }
            uint32_t bf[8][2];
            #pragma unroll
            for (int nt2 = 0; nt2 < 4; nt2++) {
                uint32_t addr = sB + swz((uint32_t)((b_row + nt2 * 16) * 128
                                                    + k16 * 32 + b_kb));
                uint32_t q0, q1, q2, q3;
                ldmx4(q0, q1, q2, q3, addr);
                bf[nt2 * 2 + 0][0] = q0; bf[nt2 * 2 + 0][1] = q1;
                bf[nt2 * 2 + 1][0] = q2; bf[nt2 * 2 + 1][1] = q3;
            }
            #pragma unroll
            for (int mt = 0; mt < 2; mt++)
                #pragma unroll
                for (int nt = 0; nt < 8; nt++)
                    mma16816(acc[mt][nt], af[mt], bf[nt][0], bf[nt][1]);
        }
    }

    const int nbase = (bn & 3) * 128;
    const float* __restrict__ bia = (sel == 0) ? bq : bk;
    __half* __restrict__ dst = (sel == 0) ? g_Qh : g_Kh;
    const int head = (nbase + wn * 64) >> 6;
    const float scale = (sel == 0) ? (1.0f / (8.0f * expf(beta[head]))) : 1.0f;

    #pragma unroll
    for (int mt = 0; mt < 2; mt++) {
        const int m0 = bm * 128 + wm * 32 + mt * 16 + g;
        #pragma unroll
        for (int nt = 0; nt < 8; nt++) {
            const int nm   = nbase + wn * 64 + nt * 8 + t * 2;
            const int dcol = nm & 63;
            const float b0v = bia[nm], b1v = bia[nm + 1];
            #pragma unroll
            for (int half = 0; half < 2; half++) {
                const int m = m0 + half * 8;
                const int s_idx = m >> 1;
                const int b_idx = m & 1;
                const float ox = (acc[mt][nt][half * 2 + 0] + b0v) * scale;
                const float oy = (acc[mt][nt][half * 2 + 1] + b1v) * scale;
                *(__half2*)&dst[((size_t)(b_idx * NHEADS + head) * S_LEN + s_idx)
                                * DHEAD + dcol] = __floats2half2_rn(ox, oy);
            }
        }
    }
}

// ---------------------------------------------------------------------------
// Kernel C: compute w(s)=sigmoid(q·k), accumulate y = Σ w·x (fp32, exact) and
// S = Σ w. Last block per z: combine partials; k2 = Wk_h·y + S·bk_h and
// v2 = Wv_h·y + S·bv_h (exact fp32); exact window scores via u = Wq_h^T k2;
// sink-softmax -> g_c; v2 -> g_v2.
// ---------------------------------------------------------------------------
__global__ __launch_bounds__(256) void reduce_kv(
    const float* __restrict__ x,
    const float* __restrict__ Wq, const float* __restrict__ bq,
    const float* __restrict__ Wk, const float* __restrict__ bk,
    const float* __restrict__ Wv, const float* __restrict__ bv,
    const float* __restrict__ beta)
{
    const int z = blockIdx.x;
    const int c = blockIdx.y;
    const int t = threadIdx.x;
    const int squad = t >> 2;
    const int dpart = (t & 3) * 16;
    const int h = z & 7;
    const int b = z >> 3;
    const int s0 = c * 128;

    __shared__ __align__(16) float s_w[128];

    // Phase 1: sigmoid weights for 128 s positions (4 threads per s).
    {
        const __half* __restrict__ Q = g_Qh + (size_t)z * S_LEN * DHEAD + dpart;
        const __half* __restrict__ K = g_Kh + (size_t)z * S_LEN * DHEAD + dpart;
        #pragma unroll
        for (int it = 0; it < 2; it++) {
            const size_t base = (size_t)(s0 + it * 64 + squad) * DHEAD;
            float qf[16], kf[16];
            ld16h(Q + base, qf);
            ld16h(K + base, kf);
            float dot = 0.f;
            #pragma unroll
            for (int j = 0; j < 16; j++) dot = fmaf(qf[j], kf[j], dot);
            dot += __shfl_xor_sync(0xFFFFFFFFu, dot, 1);
            dot += __shfl_xor_sync(0xFFFFFFFFu, dot, 2);
            if ((t & 3) == 0)
                s_w[it * 64 + squad] = 1.0f / (1.0f + expf(-dot));
        }
    }
    __syncthreads();

    // Phase 2: y[2t,2t+1] = sum_s w[s] * x[s0+s, b, 2t:2t+2];  S = sum_s w.
    {
        float2 y = {0.f, 0.f};
        const float* __restrict__ xb =
            x + ((size_t)s0 * BSZ + b) * DMODEL + 2 * t;
        #pragma unroll 4
        for (int s = 0; s < 128; s++) {
            const float w = s_w[s];
            const float2 xv = *(const float2*)(xb + (size_t)s * BSZ * DMODEL);
            y.x = fmaf(w, xv.x, y.x);
            y.y = fmaf(w, xv.y, y.y);
        }
        *(float2*)&g_yp[((size_t)(z * RCHUNK + c)) * DMODEL + 2 * t] = y;
        if (t < 32) {
            float S = s_w[t] + s_w[32 + t] + s_w[64 + t] + s_w[96 + t];
            #pragma unroll
            for (int off = 16; off; off >>= 1)
                S += __shfl_xor_sync(0xFFFFFFFFu, S, off);
            if (t == 0) g_Sp[z * RCHUNK + c] = S;
        }
    }
    __threadfence();
    __syncthreads();

    // Last block per z does the exact projections + scores.
    __shared__ int s_last;
    if (t == 0) {
        const int old = atomicAdd(&g_cnt[z], 1);
        s_last = ((old & (RCHUNK - 1)) == (RCHUNK - 1)) ? 1 : 0;
        if (s_last) __threadfence();
    }
    __syncthreads();
    if (!s_last) return;

    __shared__ __align__(16) float s_y[DMODEL];
    __shared__ float s_S;
    __shared__ __align__(16) float s_k2f[DHEAD];
    __shared__ __align__(16) float s_u[DMODEL];
    __shared__ __align__(16) float s_scr[NWIN];
    __shared__ float s_bconst;

    {
        float2 ya = {0.f, 0.f};
        #pragma unroll
        for (int cc = 0; cc < RCHUNK; cc++) {
            const float2 p = *(const float2*)
                &g_yp[((size_t)(z * RCHUNK + cc)) * DMODEL + 2 * t];
            ya.x += p.x; ya.y += p.y;
        }
        s_y[2 * t] = ya.x; s_y[2 * t + 1] = ya.y;
        if (t == 0) {
            float S = 0.f;
            #pragma unroll
            for (int cc = 0; cc < RCHUNK; cc++) S += g_Sp[z * RCHUNK + cc];
            s_S = S;
        }
    }
    __syncthreads();

    // k2[d] = Wk_h[d,:]·y + S·bk ;  v2[d] = Wv_h[d,:]·y + S·bv.
    // Warp per 8 rows; lanes split k (coalesced float4).
    {
        const int lane = t & 31, warp = t >> 5;
        #pragma unroll
        for (int j = 0; j < 8; j++) {
            const int d = warp * 8 + j;
            const float* __restrict__ wkr =
                Wk + (size_t)(h * DHEAD + d) * DMODEL + lane * 4;
            const float* __restrict__ wvr =
                Wv + (size_t)(h * DHEAD + d) * DMODEL + lane * 4;
            float dk = 0.f, dv = 0.f;
            #pragma unroll
            for (int q = 0; q < 4; q++) {
                const float4 a  = *(const float4*)(wkr + q * 128);
                const float4 bb = *(const float4*)(wvr + q * 128);
                const float4 yv = *(const float4*)&s_y[lane * 4 + q * 128];
                dk = fmaf(a.x, yv.x, dk);  dk = fmaf(a.y, yv.y, dk);
                dk = fmaf(a.z, yv.z, dk);  dk = fmaf(a.w, yv.w, dk);
                dv = fmaf(bb.x, yv.x, dv); dv = fmaf(bb.y, yv.y, dv);
                dv = fmaf(bb.z, yv.z, dv); dv = fmaf(bb.w, yv.w, dv);
            }
            #pragma unroll
            for (int off = 16; off; off >>= 1) {
                dk += __shfl_xor_sync(0xFFFFFFFFu, dk, off);
                dv += __shfl_xor_sync(0xFFFFFFFFu, dv, off);
            }
            if (lane == 0) {
                s_k2f[d] = dk + s_S * bk[h * DHEAD + d];
                g_v2[z * DHEAD + d] = dv + s_S * bv[h * DHEAD + d];
            }
        }
    }
    __syncthreads();

    // u[k] = sum_d Wq[64h+d, k] * k2[d]   (lanes coalesced over k)
    {
        float u0 = 0.f, u1 = 0.f;
        const float* __restrict__ Wqh = Wq + (size_t)(h * DHEAD) * DMODEL;
        #pragma unroll 8
        for (int d = 0; d < DHEAD; d++) {
            const float kv = s_k2f[d];
            u0 = fmaf(Wqh[(size_t)d * DMODEL + t],       kv, u0);
            u1 = fmaf(Wqh[(size_t)d * DMODEL + 256 + t], kv, u1);
        }
        s_u[t] = u0;
        s_u[256 + t] = u1;
    }
    if (t < 32) {
        float p = bq[h * DHEAD + t] * s_k2f[t]
                + bq[h * DHEAD + 32 + t] * s_k2f[32 + t];
        #pragma unroll
        for (int off = 16; off; off >>= 1)
            p += __shfl_xor_sync(0xFFFFFFFFu, p, off);
        if (t == 0) s_bconst = p;
    }
    __syncthreads();

    const float rscale = 1.0f / (8.0f * expf(beta[h]));

    {   // scores: w = t>>3 (0..31), part = t&7 handles 64 k-elements
        const int w = t >> 3, part = t & 7;
        const float4* __restrict__ xrow =
            (const float4*)(x + ((size_t)(64 * w + 63) * BSZ + b) * DMODEL) + part * 16;
        const float4* __restrict__ u4 = (const float4*)s_u + part * 16;
        float s = 0.f;
        #pragma unroll
        for (int j = 0; j < 16; j++) {
            const float4 xv = xrow[j];
            const float4 uv = u4[j];
            s = fmaf(xv.x, uv.x, s); s = fmaf(xv.y, uv.y, s);
            s = fmaf(xv.z, uv.z, s); s = fmaf(xv.w, uv.w, s);
        }
        s += __shfl_xor_sync(0xFFFFFFFFu, s, 1);
        s += __shfl_xor_sync(0xFFFFFFFFu, s, 2);
        s += __shfl_xor_sync(0xFFFFFFFFu, s, 4);
        if (part == 0) s_scr[w] = (s + s_bconst) * rscale;
    }
    __syncthreads();

    if (t < 32) {
        float s = s_scr[t];
        float mx = s;
        #pragma unroll
        for (int off = 16; off; off >>= 1)
            mx = fmaxf(mx, __shfl_xor_sync(0xFFFFFFFFu, mx, off));
        mx = fmaxf(mx, 0.f);
        const float e = expf(s - mx);
        float sum = e;
        #pragma unroll
        for (int off = 16; off; off >>= 1)
            sum += __shfl_xor_sync(0xFFFFFFFFu, sum, off);
        sum += expf(-mx);
        float cc = e / sum;
        if (t == 31) cc += 1.0f;
        g_c[z * NWIN + t] = cc;
    }
}

// ---------------------------------------------------------------------------
// Kernel D: coef_atomic — 256 blocks, block (z, nc) covers n = nc*32..+31.
// ---------------------------------------------------------------------------
__global__ __launch_bounds__(256) void coef_atomic(
    const float* __restrict__ Wo, float* __restrict__ out)
{
    const int tid = threadIdx.x;
    const int z   = blockIdx.x >> 4;
    const int nc  = blockIdx.x & 15;
    const int h   = z & 7;
    const int batch = z >> 3;

    __shared__ __align__(16) float s_v2[DHEAD];
    __shared__ __align__(16) float s_c[NWIN];
    if (tid < DHEAD) s_v2[tid] = g_v2[z * DHEAD + tid];
    else if (tid < DHEAD + NWIN) s_c[tid - DHEAD] = g_c[z * NWIN + (tid - DHEAD)];
    __syncthreads();

    const int warp = tid >> 5;
    const int lane = tid & 31;
    const float2 v2l = *(const float2*)&s_v2[lane * 2];
    const float  cw  = s_c[lane];

    float2 wv[4];
    #pragma unroll
    for (int j = 0; j < 4; j++) {
        const int n = nc * 32 + warp * 4 + j;
        wv[j] = *(const float2*)(Wo + (size_t)n * DMODEL + h * DHEAD + lane * 2);
    }
    float dot[4];
    #pragma unroll
    for (int j = 0; j < 4; j++)
        dot[j] = v2l.x * wv[j].x + v2l.y * wv[j].y;
    #pragma unroll
    for (int off = 16; off; off >>= 1)
        #pragma unroll
        for (int j = 0; j < 4; j++)
            dot[j] += __shfl_xor_sync(0xFFFFFFFFu, dot[j], off);
    #pragma unroll
    for (int j = 0; j < 4; j++) {
        const int n = nc * 32 + warp * 4 + j;
        atomicAdd(&out[((size_t)((2016 + lane) * BSZ + batch)) * DMODEL + n],
                  cw * dot[j]);
    }
}

// ---------------------------------------------------------------------------
extern "C" void kernel_launch(void* const* d_in, const int* in_sizes, int n_in,
                              void* d_out, int out_size)
{
    const float* x    = (const float*)d_in[0];
    const float* Wq   = (const float*)d_in[1];
    const float* bq   = (const float*)d_in[2];
    const float* Wk   = (const float*)d_in[3];
    const float* bk   = (const float*)d_in[4];
    const float* Wv   = (const float*)d_in[5];
    const float* bv   = (const float*)d_in[6];
    const float* Wo   = (const float*)d_in[7];
    const float* bo   = (const float*)d_in[8];
    const float* beta = (const float*)d_in[9];
    float* out = (float*)d_out;

    cudaFuncSetAttribute(gemm_mma, cudaFuncAttributeMaxDynamicSharedMemorySize,
                         SMEM_BYTES);

    convert_xw<<<K1_BLOCKS, 256>>>(x, Wq, Wk, out, bo);
    gemm_mma<<<dim3(NTOT / 128, MROWS / 128), 256, SMEM_BYTES>>>(bq, bk, beta);
    reduce_kv<<<dim3(ZB, RCHUNK), 256>>>(x, Wq, bq, Wk, bk, Wv, bv, beta);
    coef_atomic<<<256, 256>>>(Wo, out);
}

// round 16
// speedup vs baseline: 1.0861x; 1.0861x over previous
#include <cuda_runtime.h>
#include <cuda_fp16.h>
#include <math.h>
#include <stdint.h>

#define S_LEN  2048
#define BSZ    2
#define DMODEL 512
#define NHEADS 8
#define DHEAD  64
#define ZB     (BSZ*NHEADS)          // 16
#define MROWS  (S_LEN*BSZ)           // 4096
#define NWIN   32
#define KSX    512                   // X row: fp16
#define KSW    512                   // W row: fp16
#define NTOT   1024                  // Q,K columns only (V eliminated)
#define KC     64                    // K chunk (fp16) = 128B rows
#define NCHUNK 8
#define STAGES 3
#define ATILE  16384                 // 128 x 64 fp16
#define BTILE  16384
#define STAGE_BYTES (ATILE+BTILE)
#define SMEM_BYTES  (STAGES*STAGE_BYTES)   // 96 KB
#define RCH    64                    // s-chunks per batch (32 s each)
#define SCH    32                    // s per chunk

// Kernel-1 block roles
#define XCV_BLOCKS  512              // X convert: 4 float4 / thread
#define WCV_BLOCKS  512              // Wq+Wk convert: 1 float4 / thread
#define FIL_BLOCKS  512              // bias fill of ALL 2048 rows
#define K1_BLOCKS   (XCV_BLOCKS + WCV_BLOCKS + FIL_BLOCKS)   // 1536

// ---------------- static scratch (no cudaMalloc allowed) -------------------
__device__ __align__(16) __half g_Xc[(size_t)MROWS*KSX];  // 4.2 MB
__device__ __align__(16) __half g_Wc[(size_t)NTOT*KSW];   // 1.0 MB
__device__ __align__(16) __half g_Qh[(size_t)ZB*S_LEN*DHEAD];  // fp16 Q (scaled)
__device__ __align__(16) __half g_Kh[(size_t)ZB*S_LEN*DHEAD];  // fp16 K
__device__ __align__(16) float g_yp[(size_t)ZB*RCH*DMODEL];    // y partials 8MB
__device__ float g_Sp[ZB*RCH];                                 // S partials
__device__ __align__(16) float g_v2[ZB*DHEAD];
__device__ __align__(16) float g_c[ZB*NWIN];

// ---------------- helpers ---------------------------------------------------
__device__ __forceinline__ uint32_t smem_u32(const void* p) {
    uint32_t a;
    asm("{ .reg .u64 t; cvta.to.shared.u64 t, %1; cvt.u32.u64 %0, t; }"
        : "=r"(a) : "l"(p));
    return a;
}
__device__ __forceinline__ uint32_t swz(uint32_t off) {
    return off ^ ((off >> 3) & 0x70);      // SW128
}
__device__ __forceinline__ void cp16(uint32_t saddr, const void* g) {
    asm volatile("cp.async.cg.shared.global [%0], [%1], 16;"
                 :: "r"(saddr), "l"(g) : "memory");
}
#define CP_COMMIT() asm volatile("cp.async.commit_group;" ::: "memory")
#define CP_WAIT(n)  asm volatile("cp.async.wait_group %0;" :: "n"(n) : "memory")

__device__ __forceinline__ void ldmx4(uint32_t& r0, uint32_t& r1,
                                      uint32_t& r2, uint32_t& r3, uint32_t a) {
    asm volatile("ldmatrix.sync.aligned.m8n8.x4.shared.b16 {%0,%1,%2,%3}, [%4];"
                 : "=r"(r0), "=r"(r1), "=r"(r2), "=r"(r3) : "r"(a));
}
__device__ __forceinline__ void mma16816(float* c, const uint32_t* a,
                                         uint32_t b0, uint32_t b1) {
    asm volatile(
        "mma.sync.aligned.m16n8k16.row.col.f32.f16.f16.f32 "
        "{%0,%1,%2,%3}, {%4,%5,%6,%7}, {%8,%9}, {%0,%1,%2,%3};"
        : "+f"(c[0]), "+f"(c[1]), "+f"(c[2]), "+f"(c[3])
        : "r"(a[0]), "r"(a[1]), "r"(a[2]), "r"(a[3]), "r"(b0), "r"(b1));
}
// Load 16 consecutive halves (32B, 16B-aligned) and widen to float[16].
__device__ __forceinline__ void ld16h(const __half* p, float* f) {
    const uint4 u0 = *(const uint4*)p;
    const uint4 u1 = *(const uint4*)(p + 8);
    const __half2* h0 = (const __half2*)&u0;
    const __half2* h1 = (const __half2*)&u1;
    #pragma unroll
    for (int i = 0; i < 4; i++) {
        const float2 a = __half22float2(h0[i]);
        f[i * 2] = a.x; f[i * 2 + 1] = a.y;
    }
    #pragma unroll
    for (int i = 0; i < 4; i++) {
        const float2 a = __half22float2(h1[i]);
        f[8 + i * 2] = a.x; f[8 + i * 2 + 1] = a.y;
    }
}

// ---------------------------------------------------------------------------
// Kernel A: converts + bias fill (unchanged from R15).
// ---------------------------------------------------------------------------
__global__ __launch_bounds__(256) void convert_xw(
    const float* __restrict__ x,
    const float* __restrict__ Wq, const float* __restrict__ Wk,
    float* __restrict__ out, const float* __restrict__ bo)
{
    const int tid = threadIdx.x;
    const int bid = blockIdx.x;
    const int W4PM = DMODEL / 4;

    if (bid < XCV_BLOCKS) {
        #pragma unroll
        for (int j = 0; j < 4; j++) {
            const int tid4 = bid * 1024 + j * 256 + tid;
            const float4 v = ((const float4*)x)[tid4];
            const int m    = tid4 / W4PM;
            const int koff = (tid4 % W4PM) * 4;
            __half2 hi01 = __halves2half2(__float2half_rn(v.x), __float2half_rn(v.y));
            __half2 hi23 = __halves2half2(__float2half_rn(v.z), __float2half_rn(v.w));
            __half2* d0 = (__half2*)(g_Xc + (size_t)m * KSX + koff);
            d0[0] = hi01; d0[1] = hi23;
        }
    } else if (bid < XCV_BLOCKS + WCV_BLOCKS) {
        const int wi   = (bid - XCV_BLOCKS) * 256 + tid;
        const int n    = wi / W4PM;
        const int koff = (wi % W4PM) * 4;
        const int sel  = n >> 9, row = n & 511;
        const float* W = (sel == 0) ? Wq : Wk;
        const float4 v = *(const float4*)(W + (size_t)row * DMODEL + koff);
        __half2 hi01 = __halves2half2(__float2half_rn(v.x), __float2half_rn(v.y));
        __half2 hi23 = __halves2half2(__float2half_rn(v.z), __float2half_rn(v.w));
        __half2* d0 = (__half2*)(g_Wc + (size_t)n * KSW + koff);
        d0[0] = hi01; d0[1] = hi23;
    } else {
        __shared__ __align__(16) float4 sb[128];
        if (tid < 128) sb[tid] = ((const float4*)bo)[tid];
        __syncthreads();
        const int blk = bid - (XCV_BLOCKS + WCV_BLOCKS);
        float4* out4 = (float4*)out;
        #pragma unroll
        for (int j = 0; j < 4; j++) {
            const int idx = blk * 1024 + j * 256 + tid;
            out4[idx] = sb[idx & 127];
        }
    }
}

// ---------------------------------------------------------------------------
// Kernel B: fp16 warp-MMA GEMM for Q and K only (unchanged from R15).
// ---------------------------------------------------------------------------
__global__ __launch_bounds__(256, 2) void gemm_mma(
    const float* __restrict__ bq, const float* __restrict__ bk,
    const float* __restrict__ beta)
{
    extern __shared__ __align__(1024) char smem[];
    const uint32_t sbase = smem_u32(smem);
    const int tid  = threadIdx.x;
    const int lane = tid & 31;
    const int wid  = tid >> 5;
    const int bn = blockIdx.x;           // 0..7
    const int bm = blockIdx.y;           // 0..31
    const int sel = bn >> 2;             // 0=Q,1=K

    const __half* __restrict__ Xb = g_Xc + (size_t)(bm * 128) * KSX;
    const __half* __restrict__ Wb = g_Wc + (size_t)(bn * 128) * KSW;

    const int r0  = tid >> 3;
    const int c16 = tid & 7;
    uint32_t so[4];
    #pragma unroll
    for (int j = 0; j < 4; j++)
        so[j] = swz((uint32_t)((r0 + 32 * j) * 128 + c16 * 16));

    const int wm = wid & 3;
    const int wn = wid >> 2;
    const int g  = lane >> 2;
    const int t  = lane & 3;

    const int a_row = wm * 32 + (lane & 15);
    const int a_kb  = (lane >> 4) * 16;
    const int b_row = wn * 64 + (lane & 7) + (lane >> 4) * 8;
    const int b_kb  = ((lane >> 3) & 1) * 16;

    float acc[2][8][4];
    #pragma unroll
    for (int i = 0; i < 2; i++)
        #pragma unroll
        for (int j = 0; j < 8; j++)
            #pragma unroll
            for (int q = 0; q < 4; q++) acc[i][j][q] = 0.f;

    #pragma unroll
    for (int s = 0; s < STAGES - 1; s++) {
        uint32_t sA = sbase + s * STAGE_BYTES;
        uint32_t sB = sA + ATILE;
        const __half* gA = Xb + (size_t)s * KC + c16 * 8;
        const __half* gB = Wb + (size_t)s * KC + c16 * 8;
        #pragma unroll
        for (int j = 0; j < 4; j++) {
            cp16(sA + so[j], gA + (size_t)(r0 + 32 * j) * KSX);
            cp16(sB + so[j], gB + (size_t)(r0 + 32 * j) * KSW);
        }
        CP_COMMIT();
    }

    for (int i = 0; i < NCHUNK; i++) {
        CP_WAIT(STAGES - 2);
        __syncthreads();

        const int nxt = i + STAGES - 1;
        if (nxt < NCHUNK) {
            const int st = nxt % STAGES;
            uint32_t sA = sbase + st * STAGE_BYTES;
            uint32_t sB = sA + ATILE;
            const __half* gA = Xb + (size_t)nxt * KC + c16 * 8;
            const __half* gB = Wb + (size_t)nxt * KC + c16 * 8;
            #pragma unroll
            for (int j = 0; j < 4; j++) {
                cp16(sA + so[j], gA + (size_t)(r0 + 32 * j) * KSX);
                cp16(sB + so[j], gB + (size_t)(r0 + 32 * j) * KSW);
            }
        }
        CP_COMMIT();

        const uint32_t sA = sbase + (i % STAGES) * STAGE_BYTES;
        const uint32_t sB = sA + ATILE;
        #pragma unroll
        for (int k16 = 0; k16 < 4; k16++) {
            uint32_t af[2][4];
            #pragma unroll
            for (int mt = 0; mt < 2; mt++) {
                uint32_t addr = sA + swz((uint32_t)((a_row + mt * 16) * 128
                                                    + k16 * 32 + a_kb));
                ldmx4(af[mt][0], af[mt][1], af[mt][2], af[mt][3], addr);
            }
            uint32_t bf[8][2];
            #pragma unroll
            for (int nt2 = 0; nt2 < 4; nt2++) {
                uint32_t addr = sB + swz((uint32_t)((b_row + nt2 * 16) * 128
                                                    + k16 * 32 + b_kb));
                uint32_t q0, q1, q2, q3;
                ldmx4(q0, q1, q2, q3, addr);
                bf[nt2 * 2 + 0][0] = q0; bf[nt2 * 2 + 0][1] = q1;
                bf[nt2 * 2 + 1][0] = q2; bf[nt2 * 2 + 1][1] = q3;
            }
            #pragma unroll
            for (int mt = 0; mt < 2; mt++)
                #pragma unroll
                for (int nt = 0; nt < 8; nt++)
                    mma16816(acc[mt][nt], af[mt], bf[nt][0], bf[nt][1]);
        }
    }

    const int nbase = (bn & 3) * 128;
    const float* __restrict__ bia = (sel == 0) ? bq : bk;
    __half* __restrict__ dst = (sel == 0) ? g_Qh : g_Kh;
    const int head = (nbase + wn * 64) >> 6;
    const float scale = (sel == 0) ? (1.0f / (8.0f * expf(beta[head]))) : 1.0f;

    #pragma unroll
    for (int mt = 0; mt < 2; mt++) {
        const int m0 = bm * 128 + wm * 32 + mt * 16 + g;
        #pragma unroll
        for (int nt = 0; nt < 8; nt++) {
            const int nm   = nbase + wn * 64 + nt * 8 + t * 2;
            const int dcol = nm & 63;
            const float b0v = bia[nm], b1v = bia[nm + 1];
            #pragma unroll
            for (int half = 0; half < 2; half++) {
                const int m = m0 + half * 8;
                const int s_idx = m >> 1;
                const int b_idx = m & 1;
                const float ox = (acc[mt][nt][half * 2 + 0] + b0v) * scale;
                const float oy = (acc[mt][nt][half * 2 + 1] + b1v) * scale;
                *(__half2*)&dst[((size_t)(b_idx * NHEADS + head) * S_LEN + s_idx)
                                * DHEAD + dcol] = __floats2half2_rn(ox, oy);
            }
        }
    }
}

// ---------------------------------------------------------------------------
// Kernel C: reduce — block (b, c) covers s = c*32 .. +31 for ALL 8 heads.
// Phase 1: w[h][s] = sigmoid(q·k). Phase 2: x read ONCE, accumulated into
// 8 per-head y partials + S sums.
// ---------------------------------------------------------------------------
__global__ __launch_bounds__(256) void reduce_kv(const float* __restrict__ x)
{
    const int b = blockIdx.x;            // batch
    const int c = blockIdx.y;            // chunk 0..63
    const int t = threadIdx.x;
    const int squad = t >> 2;            // 0..63
    const int dpart = (t & 3) * 16;
    const int s0 = c * SCH;

    __shared__ __align__(16) float s_w[NHEADS][SCH];

    // Phase 1: 256 dots (8 heads x 32 s), 4 passes of 64 tasks.
    #pragma unroll
    for (int pass = 0; pass < 4; pass++) {
        const int task = pass * 64 + squad;      // 0..255
        const int h = task >> 5;                 // 0..7
        const int s = task & 31;                 // 0..31
        const size_t base =
            ((size_t)(b * NHEADS + h) * S_LEN + s0 + s) * DHEAD + dpart;
        float qf[16], kf[16];
        ld16h(g_Qh + base, qf);
        ld16h(g_Kh + base, kf);
        float dot = 0.f;
        #pragma unroll
        for (int j = 0; j < 16; j++) dot = fmaf(qf[j], kf[j], dot);
        dot += __shfl_xor_sync(0xFFFFFFFFu, dot, 1);
        dot += __shfl_xor_sync(0xFFFFFFFFu, dot, 2);
        if ((t & 3) == 0)
            s_w[h][s] = 1.0f / (1.0f + expf(-dot));
    }
    __syncthreads();

    // Phase 2: y[h][2t..2t+1] accumulation; x loaded once per s.
    {
        float2 y[NHEADS];
        #pragma unroll
        for (int h = 0; h < NHEADS; h++) { y[h].x = 0.f; y[h].y = 0.f; }
        const float* __restrict__ xb =
            x + ((size_t)s0 * BSZ + b) * DMODEL + 2 * t;
        #pragma unroll 4
        for (int s = 0; s < SCH; s++) {
            const float2 xv = *(const float2*)(xb + (size_t)s * BSZ * DMODEL);
            #pragma unroll
            for (int h = 0; h < NHEADS; h++) {
                const float w = s_w[h][s];
                y[h].x = fmaf(w, xv.x, y[h].x);
                y[h].y = fmaf(w, xv.y, y[h].y);
            }
        }
        #pragma unroll
        for (int h = 0; h < NHEADS; h++) {
            *(float2*)&g_yp[((size_t)((b * NHEADS + h) * RCH + c)) * DMODEL
                            + 2 * t] = y[h];
        }
    }
    // S sums: warp 0, lane l: h = l>>2, part = l&3 covers 8 s each.
    if (t < 32) {
        const int h = t >> 2, part = t & 3;
        float S = 0.f;
        #pragma unroll
        for (int j = 0; j < 8; j++) S += s_w[h][part * 8 + j];
        S += __shfl_xor_sync(0xFFFFFFFFu, S, 1);
        S += __shfl_xor_sync(0xFFFFFFFFu, S, 2);
        if (part == 0) g_Sp[(b * NHEADS + h) * RCH + c] = S;
    }
}

// ---------------------------------------------------------------------------
// Kernel D: finalize — one block per z. Combine y/S partials; exact
// k2 = Wk_h·y + S·bk, v2 = Wv_h·y + S·bv; u = Wq_h^T k2; exact scores;
// sink-softmax -> g_c; v2 -> g_v2.
// ---------------------------------------------------------------------------
__global__ __launch_bounds__(256) void finalize(
    const float* __restrict__ x,
    const float* __restrict__ Wq, const float* __restrict__ bq,
    const float* __restrict__ Wk, const float* __restrict__ bk,
    const float* __restrict__ Wv, const float* __restrict__ bv,
    const float* __restrict__ beta)
{
    const int z = blockIdx.x;
    const int t = threadIdx.x;
    const int h = z & 7;
    const int b = z >> 3;

    __shared__ __align__(16) float s_y[DMODEL];
    __shared__ float s_S;
    __shared__ __align__(16) float s_k2f[DHEAD];
    __shared__ __align__(16) float s_u[DMODEL];
    __shared__ __align__(16) float s_scr[NWIN];
    __shared__ float s_bconst;

    {
        float2 ya = {0.f, 0.f};
        #pragma unroll 8
        for (int cc = 0; cc < RCH; cc++) {
            const float2 p = *(const float2*)
                &g_yp[((size_t)(z * RCH + cc)) * DMODEL + 2 * t];
            ya.x += p.x; ya.y += p.y;
        }
        s_y[2 * t] = ya.x; s_y[2 * t + 1] = ya.y;
    }
    if (t < 32) {
        float S = g_Sp[z * RCH + t] + g_Sp[z * RCH + 32 + t];
        #pragma unroll
        for (int off = 16; off; off >>= 1)
            S += __shfl_xor_sync(0xFFFFFFFFu, S, off);
        if (t == 0) s_S = S;
    }
    __syncthreads();

    // k2[d] / v2[d] matvecs: warp per 8 rows; lanes split k (coalesced).
    {
        const int lane = t & 31, warp = t >> 5;
        #pragma unroll
        for (int j = 0; j < 8; j++) {
            const int d = warp * 8 + j;
            const float* __restrict__ wkr =
                Wk + (size_t)(h * DHEAD + d) * DMODEL + lane * 4;
            const float* __restrict__ wvr =
                Wv + (size_t)(h * DHEAD + d) * DMODEL + lane * 4;
            float dk = 0.f, dv = 0.f;
            #pragma unroll
            for (int q = 0; q < 4; q++) {
                const float4 a  = *(const float4*)(wkr + q * 128);
                const float4 bb = *(const float4*)(wvr + q * 128);
                const float4 yv = *(const float4*)&s_y[lane * 4 + q * 128];
                dk = fmaf(a.x, yv.x, dk);  dk = fmaf(a.y, yv.y, dk);
                dk = fmaf(a.z, yv.z, dk);  dk = fmaf(a.w, yv.w, dk);
                dv = fmaf(bb.x, yv.x, dv); dv = fmaf(bb.y, yv.y, dv);
                dv = fmaf(bb.z, yv.z, dv); dv = fmaf(bb.w, yv.w, dv);
            }
            #pragma unroll
            for (int off = 16; off; off >>= 1) {
                dk += __shfl_xor_sync(0xFFFFFFFFu, dk, off);
                dv += __shfl_xor_sync(0xFFFFFFFFu, dv, off);
            }
            if (lane == 0) {
                s_k2f[d] = dk + s_S * bk[h * DHEAD + d];
                g_v2[z * DHEAD + d] = dv + s_S * bv[h * DHEAD + d];
            }
        }
    }
    __syncthreads();

    // u[k] = sum_d Wq[64h+d, k] * k2[d]
    {
        float u0 = 0.f, u1 = 0.f;
        const float* __restrict__ Wqh = Wq + (size_t)(h * DHEAD) * DMODEL;
        #pragma unroll 8
        for (int d = 0; d < DHEAD; d++) {
            const float kv = s_k2f[d];
            u0 = fmaf(Wqh[(size_t)d * DMODEL + t],       kv, u0);
            u1 = fmaf(Wqh[(size_t)d * DMODEL + 256 + t], kv, u1);
        }
        s_u[t] = u0;
        s_u[256 + t] = u1;
    }
    if (t < 32) {
        float p = bq[h * DHEAD + t] * s_k2f[t]
                + bq[h * DHEAD + 32 + t] * s_k2f[32 + t];
        #pragma unroll
        for (int off = 16; off; off >>= 1)
            p += __shfl_xor_sync(0xFFFFFFFFu, p, off);
        if (t == 0) s_bconst = p;
    }
    __syncthreads();

    const float rscale = 1.0f / (8.0f * expf(beta[h]));

    {   // scores: w = t>>3 (0..31), part = t&7 handles 64 k-elements
        const int w = t >> 3, part = t & 7;
        const float4* __restrict__ xrow =
            (const float4*)(x + ((size_t)(64 * w + 63) * BSZ + b) * DMODEL) + part * 16;
        const float4* __restrict__ u4 = (const float4*)s_u + part * 16;
        float s = 0.f;
        #pragma unroll
        for (int j = 0; j < 16; j++) {
            const float4 xv = xrow[j];
            const float4 uv = u4[j];
            s = fmaf(xv.x, uv.x, s); s = fmaf(xv.y, uv.y, s);
            s = fmaf(xv.z, uv.z, s); s = fmaf(xv.w, uv.w, s);
        }
        s += __shfl_xor_sync(0xFFFFFFFFu, s, 1);
        s += __shfl_xor_sync(0xFFFFFFFFu, s, 2);
        s += __shfl_xor_sync(0xFFFFFFFFu, s, 4);
        if (part == 0) s_scr[w] = (s + s_bconst) * rscale;
    }
    __syncthreads();

    if (t < 32) {
        float s = s_scr[t];
        float mx = s;
        #pragma unroll
        for (int off = 16; off; off >>= 1)
            mx = fmaxf(mx, __shfl_xor_sync(0xFFFFFFFFu, mx, off));
        mx = fmaxf(mx, 0.f);
        const float e = expf(s - mx);
        float sum = e;
        #pragma unroll
        for (int off = 16; off; off >>= 1)
            sum += __shfl_xor_sync(0xFFFFFFFFu, sum, off);
        sum += expf(-mx);
        float cc = e / sum;
        if (t == 31) cc += 1.0f;
        g_c[z * NWIN + t] = cc;
    }
}

// ---------------------------------------------------------------------------
// Kernel E: coef_atomic — 256 blocks, block (z, nc) covers n = nc*32..+31.
// ---------------------------------------------------------------------------
__global__ __launch_bounds__(256) void coef_atomic(
    const float* __restrict__ Wo, float* __restrict__ out)
{
    const int tid = threadIdx.x;
    const int z   = blockIdx.x >> 4;
    const int nc  = blockIdx.x & 15;
    const int h   = z & 7;
    const int batch = z >> 3;

    __shared__ __align__(16) float s_v2[DHEAD];
    __shared__ __align__(16) float s_c[NWIN];
    if (tid < DHEAD) s_v2[tid] = g_v2[z * DHEAD + tid];
    else if (tid < DHEAD + NWIN) s_c[tid - DHEAD] = g_c[z * NWIN + (tid - DHEAD)];
    __syncthreads();

    const int warp = tid >> 5;
    const int lane = tid & 31;
    const float2 v2l = *(const float2*)&s_v2[lane * 2];
    const float  cw  = s_c[lane];

    float2 wv[4];
    #pragma unroll
    for (int j = 0; j < 4; j++) {
        const int n = nc * 32 + warp * 4 + j;
        wv[j] = *(const float2*)(Wo + (size_t)n * DMODEL + h * DHEAD + lane * 2);
    }
    float dot[4];
    #pragma unroll
    for (int j = 0; j < 4; j++)
        dot[j] = v2l.x * wv[j].x + v2l.y * wv[j].y;
    #pragma unroll
    for (int off = 16; off; off >>= 1)
        #pragma unroll
        for (int j = 0; j < 4; j++)
            dot[j] += __shfl_xor_sync(0xFFFFFFFFu, dot[j], off);
    #pragma unroll
    for (int j = 0; j < 4; j++) {
        const int n = nc * 32 + warp * 4 + j;
        atomicAdd(&out[((size_t)((2016 + lane) * BSZ + batch)) * DMODEL + n],
                  cw * dot[j]);
    }
}

// ---------------------------------------------------------------------------
extern "C" void kernel_launch(void* const* d_in, const int* in_sizes, int n_in,
                              void* d_out, int out_size)
{
    const float* x    = (const float*)d_in[0];
    const float* Wq   = (const float*)d_in[1];
    const float* bq   = (const float*)d_in[2];
    const float* Wk   = (const float*)d_in[3];
    const float* bk   = (const float*)d_in[4];
    const float* Wv   = (const float*)d_in[5];
    const float* bv   = (const float*)d_in[6];
    const float* Wo   = (const float*)d_in[7];
    const float* bo   = (const float*)d_in[8];
    const float* beta = (const float*)d_in[9];
    float* out = (float*)d_out;

    cudaFuncSetAttribute(gemm_mma, cudaFuncAttributeMaxDynamicSharedMemorySize,
                         SMEM_BYTES);

    convert_xw<<<K1_BLOCKS, 256>>>(x, Wq, Wk, out, bo);
    gemm_mma<<<dim3(NTOT / 128, MROWS / 128), 256, SMEM_BYTES>>>(bq, bk, beta);
    reduce_kv<<<dim3(BSZ, RCH), 256>>>(x);
    finalize<<<ZB, 256>>>(x, Wq, bq, Wk, bk, Wv, bv, beta);
    coef_atomic<<<256, 256>>>(Wo, out);
}

// round 17
// speedup vs baseline: 1.1884x; 1.0942x over previous
#include <cuda_runtime.h>
#include <cuda_fp16.h>
#include <math.h>
#include <stdint.h>

#define S_LEN  2048
#define BSZ    2
#define DMODEL 512
#define NHEADS 8
#define DHEAD  64
#define ZB     (BSZ*NHEADS)          // 16
#define MROWS  (S_LEN*BSZ)           // 4096
#define NWIN   32
#define KSX    512                   // X row: fp16
#define KSW    512                   // W row: fp16
#define NTOT   1024                  // Q,K columns only (V eliminated)
#define KC     64                    // K chunk (fp16) = 128B rows
#define NCHUNK 8
#define STAGES 3
#define ATILE  16384                 // 128 x 64 fp16
#define BTILE  16384
#define STAGE_BYTES (ATILE+BTILE)
#define SMEM_BYTES  (STAGES*STAGE_BYTES)   // 96 KB
#define RCH    64                    // s-chunks per batch (32 s each)
#define SCH    32                    // s per chunk

// Kernel-1 block roles
#define XCV_BLOCKS  512
#define WCV_BLOCKS  512
#define FIL_BLOCKS  512
#define K1_BLOCKS   (XCV_BLOCKS + WCV_BLOCKS + FIL_BLOCKS)   // 1536

// ---------------- static scratch (no cudaMalloc allowed) -------------------
__device__ __align__(16) __half g_Xc[(size_t)MROWS*KSX];  // 4.2 MB
__device__ __align__(16) __half g_Wc[(size_t)NTOT*KSW];   // 1.0 MB
__device__ __align__(16) __half g_Qh[(size_t)ZB*S_LEN*DHEAD];  // fp16 Q (scaled)
__device__ __align__(16) __half g_Kh[(size_t)ZB*S_LEN*DHEAD];  // fp16 K
__device__ __align__(16) float g_yp[(size_t)ZB*RCH*DMODEL];    // y partials 8MB
__device__ float g_Sp[ZB*RCH];                                 // S partials
__device__ __align__(16) float g_k2[ZB*DHEAD];
__device__ __align__(16) float g_v2[ZB*DHEAD];
__device__ __align__(16) float g_scr[ZB*NWIN];                 // raw scores

// ---------------- helpers ---------------------------------------------------
__device__ __forceinline__ uint32_t smem_u32(const void* p) {
    uint32_t a;
    asm("{ .reg .u64 t; cvta.to.shared.u64 t, %1; cvt.u32.u64 %0, t; }"
        : "=r"(a) : "l"(p));
    return a;
}
__device__ __forceinline__ uint32_t swz(uint32_t off) {
    return off ^ ((off >> 3) & 0x70);      // SW128
}
__device__ __forceinline__ void cp16(uint32_t saddr, const void* g) {
    asm volatile("cp.async.cg.shared.global [%0], [%1], 16;"
                 :: "r"(saddr), "l"(g) : "memory");
}
#define CP_COMMIT() asm volatile("cp.async.commit_group;" ::: "memory")
#define CP_WAIT(n)  asm volatile("cp.async.wait_group %0;" :: "n"(n) : "memory")

__device__ __forceinline__ void ldmx4(uint32_t& r0, uint32_t& r1,
                                      uint32_t& r2, uint32_t& r3, uint32_t a) {
    asm volatile("ldmatrix.sync.aligned.m8n8.x4.shared.b16 {%0,%1,%2,%3}, [%4];"
                 : "=r"(r0), "=r"(r1), "=r"(r2), "=r"(r3) : "r"(a));
}
__device__ __forceinline__ void mma16816(float* c, const uint32_t* a,
                                         uint32_t b0, uint32_t b1) {
    asm volatile(
        "mma.sync.aligned.m16n8k16.row.col.f32.f16.f16.f32 "
        "{%0,%1,%2,%3}, {%4,%5,%6,%7}, {%8,%9}, {%0,%1,%2,%3};"
        : "+f"(c[0]), "+f"(c[1]), "+f"(c[2]), "+f"(c[3])
        : "r"(a[0]), "r"(a[1]), "r"(a[2]), "r"(a[3]), "r"(b0), "r"(b1));
}
// Load 16 consecutive halves (32B, 16B-aligned) and widen to float[16].
__device__ __forceinline__ void ld16h(const __half* p, float* f) {
    const uint4 u0 = *(const uint4*)p;
    const uint4 u1 = *(const uint4*)(p + 8);
    const __half2* h0 = (const __half2*)&u0;
    const __half2* h1 = (const __half2*)&u1;
    #pragma unroll
    for (int i = 0; i < 4; i++) {
        const float2 a = __half22float2(h0[i]);
        f[i * 2] = a.x; f[i * 2 + 1] = a.y;
    }
    #pragma unroll
    for (int i = 0; i < 4; i++) {
        const float2 a = __half22float2(h1[i]);
        f[8 + i * 2] = a.x; f[8 + i * 2 + 1] = a.y;
    }
}

// ---------------------------------------------------------------------------
// Kernel A: converts + bias fill.
// ---------------------------------------------------------------------------
__global__ __launch_bounds__(256) void convert_xw(
    const float* __restrict__ x,
    const float* __restrict__ Wq, const float* __restrict__ Wk,
    float* __restrict__ out, const float* __restrict__ bo)
{
    const int tid = threadIdx.x;
    const int bid = blockIdx.x;
    const int W4PM = DMODEL / 4;

    if (bid < XCV_BLOCKS) {
        #pragma unroll
        for (int j = 0; j < 4; j++) {
            const int tid4 = bid * 1024 + j * 256 + tid;
            const float4 v = ((const float4*)x)[tid4];
            const int m    = tid4 / W4PM;
            const int koff = (tid4 % W4PM) * 4;
            __half2 hi01 = __halves2half2(__float2half_rn(v.x), __float2half_rn(v.y));
            __half2 hi23 = __halves2half2(__float2half_rn(v.z), __float2half_rn(v.w));
            __half2* d0 = (__half2*)(g_Xc + (size_t)m * KSX + koff);
            d0[0] = hi01; d0[1] = hi23;
        }
    } else if (bid < XCV_BLOCKS + WCV_BLOCKS) {
        const int wi   = (bid - XCV_BLOCKS) * 256 + tid;
        const int n    = wi / W4PM;
        const int koff = (wi % W4PM) * 4;
        const int sel  = n >> 9, row = n & 511;
        const float* W = (sel == 0) ? Wq : Wk;
        const float4 v = *(const float4*)(W + (size_t)row * DMODEL + koff);
        __half2 hi01 = __halves2half2(__float2half_rn(v.x), __float2half_rn(v.y));
        __half2 hi23 = __halves2half2(__float2half_rn(v.z), __float2half_rn(v.w));
        __half2* d0 = (__half2*)(g_Wc + (size_t)n * KSW + koff);
        d0[0] = hi01; d0[1] = hi23;
    } else {
        __shared__ __align__(16) float4 sb[128];
        if (tid < 128) sb[tid] = ((const float4*)bo)[tid];
        __syncthreads();
        const int blk = bid - (XCV_BLOCKS + WCV_BLOCKS);
        float4* out4 = (float4*)out;
        #pragma unroll
        for (int j = 0; j < 4; j++) {
            const int idx = blk * 1024 + j * 256 + tid;
            out4[idx] = sb[idx & 127];
        }
    }
}

// ---------------------------------------------------------------------------
// Kernel B: fp16 warp-MMA GEMM for Q and K only.
// ---------------------------------------------------------------------------
__global__ __launch_bounds__(256, 2) void gemm_mma(
    const float* __restrict__ bq, const float* __restrict__ bk,
    const float* __restrict__ beta)
{
    extern __shared__ __align__(1024) char smem[];
    const uint32_t sbase = smem_u32(smem);
    const int tid  = threadIdx.x;
    const int lane = tid & 31;
    const int wid  = tid >> 5;
    const int bn = blockIdx.x;           // 0..7
    const int bm = blockIdx.y;           // 0..31
    const int sel = bn >> 2;             // 0=Q,1=K

    const __half* __restrict__ Xb = g_Xc + (size_t)(bm * 128) * KSX;
    const __half* __restrict__ Wb = g_Wc + (size_t)(bn * 128) * KSW;

    const int r0  = tid >> 3;
    const int c16 = tid & 7;
    uint32_t so[4];
    #pragma unroll
    for (int j = 0; j < 4; j++)
        so[j] = swz((uint32_t)((r0 + 32 * j) * 128 + c16 * 16));

    const int wm = wid & 3;
    const int wn = wid >> 2;
    const int g  = lane >> 2;
    const int t  = lane & 3;

    const int a_row = wm * 32 + (lane & 15);
    const int a_kb  = (lane >> 4) * 16;
    const int b_row = wn * 64 + (lane & 7) + (lane >> 4) * 8;
    const int b_kb  = ((lane >> 3) & 1) * 16;

    float acc[2][8][4];
    #pragma unroll
    for (int i = 0; i < 2; i++)
        #pragma unroll
        for (int j = 0; j < 8; j++)
            #pragma unroll
            for (int q = 0; q < 4; q++) acc[i][j][q] = 0.f;

    #pragma unroll
    for (int s = 0; s < STAGES - 1; s++) {
        uint32_t sA = sbase + s * STAGE_BYTES;
        uint32_t sB = sA + ATILE;
        const __half* gA = Xb + (size_t)s * KC + c16 * 8;
        const __half* gB = Wb + (size_t)s * KC + c16 * 8;
        #pragma unroll
        for (int j = 0; j < 4; j++) {
            cp16(sA + so[j], gA + (size_t)(r0 + 32 * j) * KSX);
            cp16(sB + so[j], gB + (size_t)(r0 + 32 * j) * KSW);
        }
        CP_COMMIT();
    }

    for (int i = 0; i < NCHUNK; i++) {
        CP_WAIT(STAGES - 2);
        __syncthreads();

        const int nxt = i + STAGES - 1;
        if (nxt < NCHUNK) {
            const int st = nxt % STAGES;
            uint32_t sA = sbase + st * STAGE_BYTES;
            uint32_t sB = sA + ATILE;
            const __half* gA = Xb + (size_t)nxt * KC + c16 * 8;
            const __half* gB = Wb + (size_t)nxt * KC + c16 * 8;
            #pragma unroll
            for (int j = 0; j < 4; j++) {
                cp16(sA + so[j], gA + (size_t)(r0 + 32 * j) * KSX);
                cp16(sB + so[j], gB + (size_t)(r0 + 32 * j) * KSW);
            }
        }
        CP_COMMIT();

        const uint32_t sA = sbase + (i % STAGES) * STAGE_BYTES;
        const uint32_t sB = sA + ATILE;
        #pragma unroll
        for (int k16 = 0; k16 < 4; k16++) {
            uint32_t af[2][4];
            #pragma unroll
            for (int mt = 0; mt < 2; mt++) {
                uint32_t addr = sA + swz((uint32_t)((a_row + mt * 16) * 128
                                                    + k16 * 32 + a_kb));
                ldmx4(af[mt][0], af[mt][1], af[mt][2], af[mt][3], addr);
            }
            uint32_t bf[8][2];
            #pragma unroll
            for (int nt2 = 0; nt2 < 4; nt2++) {
                uint32_t addr = sB + swz((uint32_t)((b_row + nt2 * 16) * 128
                                                    + k16 * 32 + b_kb));
                uint32_t q0, q1, q2, q3;
                ldmx4(q0, q1, q2, q3, addr);
                bf[nt2 * 2 + 0][0] = q0; bf[nt2 * 2 + 0][1] = q1;
                bf[nt2 * 2 + 1][0] = q2; bf[nt2 * 2 + 1][1] = q3;
            }
            #pragma unroll
            for (int mt = 0; mt < 2; mt++)
                #pragma unroll
                for (int nt = 0; nt < 8; nt++)
                    mma16816(acc[mt][nt], af[mt], bf[nt][0], bf[nt][1]);
        }
    }

    const int nbase = (bn & 3) * 128;
    const float* __restrict__ bia = (sel == 0) ? bq : bk;
    __half* __restrict__ dst = (sel == 0) ? g_Qh : g_Kh;
    const int head = (nbase + wn * 64) >> 6;
    const float scale = (sel == 0) ? (1.0f / (8.0f * expf(beta[head]))) : 1.0f;

    #pragma unroll
    for (int mt = 0; mt < 2; mt++) {
        const int m0 = bm * 128 + wm * 32 + mt * 16 + g;
        #pragma unroll
        for (int nt = 0; nt < 8; nt++) {
            const int nm   = nbase + wn * 64 + nt * 8 + t * 2;
            const int dcol = nm & 63;
            const float b0v = bia[nm], b1v = bia[nm + 1];
            #pragma unroll
            for (int half = 0; half < 2; half++) {
                const int m = m0 + half * 8;
                const int s_idx = m >> 1;
                const int b_idx = m & 1;
                const float ox = (acc[mt][nt][half * 2 + 0] + b0v) * scale;
                const float oy = (acc[mt][nt][half * 2 + 1] + b1v) * scale;
                *(__half2*)&dst[((size_t)(b_idx * NHEADS + head) * S_LEN + s_idx)
                                * DHEAD + dcol] = __floats2half2_rn(ox, oy);
            }
        }
    }
}

// ---------------------------------------------------------------------------
// Kernel C: reduce — block (b, c) covers s = c*32 .. +31 for ALL 8 heads.
// ---------------------------------------------------------------------------
__global__ __launch_bounds__(256) void reduce_kv(const float* __restrict__ x)
{
    const int b = blockIdx.x;
    const int c = blockIdx.y;
    const int t = threadIdx.x;
    const int squad = t >> 2;
    const int dpart = (t & 3) * 16;
    const int s0 = c * SCH;

    __shared__ __align__(16) float s_w[NHEADS][SCH];

    #pragma unroll
    for (int pass = 0; pass < 4; pass++) {
        const int task = pass * 64 + squad;
        const int h = task >> 5;
        const int s = task & 31;
        const size_t base =
            ((size_t)(b * NHEADS + h) * S_LEN + s0 + s) * DHEAD + dpart;
        float qf[16], kf[16];
        ld16h(g_Qh + base, qf);
        ld16h(g_Kh + base, kf);
        float dot = 0.f;
        #pragma unroll
        for (int j = 0; j < 16; j++) dot = fmaf(qf[j], kf[j], dot);
        dot += __shfl_xor_sync(0xFFFFFFFFu, dot, 1);
        dot += __shfl_xor_sync(0xFFFFFFFFu, dot, 2);
        if ((t & 3) == 0)
            s_w[h][s] = 1.0f / (1.0f + expf(-dot));
    }
    __syncthreads();

    {
        float2 y[NHEADS];
        #pragma unroll
        for (int h = 0; h < NHEADS; h++) { y[h].x = 0.f; y[h].y = 0.f; }
        const float* __restrict__ xb =
            x + ((size_t)s0 * BSZ + b) * DMODEL + 2 * t;
        #pragma unroll 4
        for (int s = 0; s < SCH; s++) {
            const float2 xv = *(const float2*)(xb + (size_t)s * BSZ * DMODEL);
            #pragma unroll
            for (int h = 0; h < NHEADS; h++) {
                const float w = s_w[h][s];
                y[h].x = fmaf(w, xv.x, y[h].x);
                y[h].y = fmaf(w, xv.y, y[h].y);
            }
        }
        #pragma unroll
        for (int h = 0; h < NHEADS; h++) {
            *(float2*)&g_yp[((size_t)((b * NHEADS + h) * RCH + c)) * DMODEL
                            + 2 * t] = y[h];
        }
    }
    if (t < 32) {
        const int h = t >> 2, part = t & 3;
        float S = 0.f;
        #pragma unroll
        for (int j = 0; j < 8; j++) S += s_w[h][part * 8 + j];
        S += __shfl_xor_sync(0xFFFFFFFFu, S, 1);
        S += __shfl_xor_sync(0xFFFFFFFFu, S, 2);
        if (part == 0) g_Sp[(b * NHEADS + h) * RCH + c] = S;
    }
}

// ---------------------------------------------------------------------------
// Kernel D: combine_mv — grid (ZB, 8). Block (z, g): redundantly combine the
// full y (coalesced) + S, then compute k2/v2 rows d = g*8 .. +7 (warp/row).
// ---------------------------------------------------------------------------
__global__ __launch_bounds__(256) void combine_mv(
    const float* __restrict__ Wk, const float* __restrict__ bk,
    const float* __restrict__ Wv, const float* __restrict__ bv)
{
    const int z = blockIdx.x;
    const int g = blockIdx.y;
    const int t = threadIdx.x;
    const int h = z & 7;

    __shared__ __align__(16) float s_y[DMODEL];
    __shared__ float s_S;

    {
        float2 ya = {0.f, 0.f};
        #pragma unroll 8
        for (int cc = 0; cc < RCH; cc++) {
            const float2 p = *(const float2*)
                &g_yp[((size_t)(z * RCH + cc)) * DMODEL + 2 * t];
            ya.x += p.x; ya.y += p.y;
        }
        s_y[2 * t] = ya.x; s_y[2 * t + 1] = ya.y;
    }
    if (t < 32) {
        float S = g_Sp[z * RCH + t] + g_Sp[z * RCH + 32 + t];
        #pragma unroll
        for (int off = 16; off; off >>= 1)
            S += __shfl_xor_sync(0xFFFFFFFFu, S, off);
        if (t == 0) s_S = S;
    }
    __syncthreads();

    // warp j handles row d = g*8 + j
    const int lane = t & 31, warp = t >> 5;
    const int d = g * 8 + warp;
    const float* __restrict__ wkr =
        Wk + (size_t)(h * DHEAD + d) * DMODEL + lane * 4;
    const float* __restrict__ wvr =
        Wv + (size_t)(h * DHEAD + d) * DMODEL + lane * 4;
    float dk = 0.f, dv = 0.f;
    #pragma unroll
    for (int q = 0; q < 4; q++) {
        const float4 a  = *(const float4*)(wkr + q * 128);
        const float4 bb = *(const float4*)(wvr + q * 128);
        const float4 yv = *(const float4*)&s_y[lane * 4 + q * 128];
        dk = fmaf(a.x, yv.x, dk);  dk = fmaf(a.y, yv.y, dk);
        dk = fmaf(a.z, yv.z, dk);  dk = fmaf(a.w, yv.w, dk);
        dv = fmaf(bb.x, yv.x, dv); dv = fmaf(bb.y, yv.y, dv);
        dv = fmaf(bb.z, yv.z, dv); dv = fmaf(bb.w, yv.w, dv);
    }
    #pragma unroll
    for (int off = 16; off; off >>= 1) {
        dk += __shfl_xor_sync(0xFFFFFFFFu, dk, off);
        dv += __shfl_xor_sync(0xFFFFFFFFu, dv, off);
    }
    if (lane == 0) {
        g_k2[z * DHEAD + d] = dk + s_S * bk[h * DHEAD + d];
        g_v2[z * DHEAD + d] = dv + s_S * bv[h * DHEAD + d];
    }
}

// ---------------------------------------------------------------------------
// Kernel E: scores — grid (ZB, 4). Block (z, wg): exact raw scores for
// windows w = wg*8..+7:  score_w = rscale*( sum_d (Wq_h[d,:]·x_w)·k2[d]
//                                           + bq_h·k2 ).
// ---------------------------------------------------------------------------
__global__ __launch_bounds__(256) void scores(
    const float* __restrict__ x,
    const float* __restrict__ Wq, const float* __restrict__ bq,
    const float* __restrict__ beta)
{
    const int z  = blockIdx.x;
    const int wg = blockIdx.y;
    const int t  = threadIdx.x;
    const int h  = z & 7;
    const int b  = z >> 3;
    const int lane = t & 31, warp = t >> 5;

    __shared__ __align__(16) float s_k2[DHEAD];
    __shared__ __align__(16) float s_x[8][DMODEL];   // 16 KB
    __shared__ float s_part[8][8];

    if (t < DHEAD) s_k2[t] = g_k2[z * DHEAD + t];
    // load 8 window x-rows: row r, thread copies strided float4
    {
        const int r = t >> 5;                        // warp -> row
        const int w_i = wg * 8 + r;
        const float4* src = (const float4*)
            (x + ((size_t)(64 * w_i + 63) * BSZ + b) * DMODEL);
        #pragma unroll
        for (int q = 0; q < 4; q++)
            *(float4*)&s_x[r][(lane + q * 32) * 4] = src[lane + q * 32];
    }
    __syncthreads();

    // warp handles d-rows d = warp*8 + jr; 8 windows share Wq row loads.
    float accw[8];
    #pragma unroll
    for (int w = 0; w < 8; w++) accw[w] = 0.f;

    #pragma unroll
    for (int jr = 0; jr < 8; jr++) {
        const int d = warp * 8 + jr;
        const float* __restrict__ wqr =
            Wq + (size_t)(h * DHEAD + d) * DMODEL + lane * 4;
        float4 wq[4];
        #pragma unroll
        for (int q = 0; q < 4; q++) wq[q] = *(const float4*)(wqr + q * 128);

        float dot[8];
        #pragma unroll
        for (int w = 0; w < 8; w++) {
            float s = 0.f;
            #pragma unroll
            for (int q = 0; q < 4; q++) {
                const float4 xv = *(const float4*)&s_x[w][lane * 4 + q * 128];
                s = fmaf(wq[q].x, xv.x, s); s = fmaf(wq[q].y, xv.y, s);
                s = fmaf(wq[q].z, xv.z, s); s = fmaf(wq[q].w, xv.w, s);
            }
            dot[w] = s;
        }
        #pragma unroll
        for (int off = 16; off; off >>= 1)
            #pragma unroll
            for (int w = 0; w < 8; w++)
                dot[w] += __shfl_xor_sync(0xFFFFFFFFu, dot[w], off);
        const float k2d = s_k2[d];
        #pragma unroll
        for (int w = 0; w < 8; w++)
            accw[w] = fmaf(dot[w], k2d, accw[w]);
    }
    if (lane < 8) s_part[warp][lane] = accw[lane];
    __syncthreads();

    if (t < 8) {
        float sc = 0.f;
        #pragma unroll
        for (int j = 0; j < 8; j++) sc += s_part[j][t];
        float bconst = 0.f;
        #pragma unroll
        for (int d = 0; d < DHEAD; d++)
            bconst = fmaf(bq[h * DHEAD + d], s_k2[d], bconst);
        const float rscale = 1.0f / (8.0f * expf(beta[h]));
        g_scr[z * NWIN + wg * 8 + t] = (sc + bconst) * rscale;
    }
}

// ---------------------------------------------------------------------------
// Kernel F: coef_atomic — 256 blocks, block (z, nc) covers n = nc*32..+31.
// Recomputes the (trivial) sink-softmax from raw scores per block.
// ---------------------------------------------------------------------------
__global__ __launch_bounds__(256) void coef_atomic(
    const float* __restrict__ Wo, float* __restrict__ out)
{
    const int tid = threadIdx.x;
    const int z   = blockIdx.x >> 4;
    const int nc  = blockIdx.x & 15;
    const int h   = z & 7;
    const int batch = z >> 3;

    __shared__ __align__(16) float s_v2[DHEAD];
    __shared__ __align__(16) float s_c[NWIN];
    if (tid < DHEAD) s_v2[tid] = g_v2[z * DHEAD + tid];
    __syncthreads();

    if (tid < 32) {   // warp 0: softmax with sink
        float s = g_scr[z * NWIN + tid];
        float mx = s;
        #pragma unroll
        for (int off = 16; off; off >>= 1)
            mx = fmaxf(mx, __shfl_xor_sync(0xFFFFFFFFu, mx, off));
        mx = fmaxf(mx, 0.f);
        const float e = expf(s - mx);
        float sum = e;
        #pragma unroll
        for (int off = 16; off; off >>= 1)
            sum += __shfl_xor_sync(0xFFFFFFFFu, sum, off);
        sum += expf(-mx);
        float cc = e / sum;
        if (tid == 31) cc += 1.0f;
        s_c[tid] = cc;
    }
    __syncthreads();

    const int warp = tid >> 5;
    const int lane = tid & 31;
    const float2 v2l = *(const float2*)&s_v2[lane * 2];
    const float  cw  = s_c[lane];

    float2 wv[4];
    #pragma unroll
    for (int j = 0; j < 4; j++) {
        const int n = nc * 32 + warp * 4 + j;
        wv[j] = *(const float2*)(Wo + (size_t)n * DMODEL + h * DHEAD + lane * 2);
    }
    float dot[4];
    #pragma unroll
    for (int j = 0; j < 4; j++)
        dot[j] = v2l.x * wv[j].x + v2l.y * wv[j].y;
    #pragma unroll
    for (int off = 16; off; off >>= 1)
        #pragma unroll
        for (int j = 0; j < 4; j++)
            dot[j] += __shfl_xor_sync(0xFFFFFFFFu, dot[j], off);
    #pragma unroll
    for (int j = 0; j < 4; j++) {
        const int n = nc * 32 + warp * 4 + j;
        atomicAdd(&out[((size_t)((2016 + lane) * BSZ + batch)) * DMODEL + n],
                  cw * dot[j]);
    }
}

// ---------------------------------------------------------------------------
extern "C" void kernel_launch(void* const* d_in, const int* in_sizes, int n_in,
                              void* d_out, int out_size)
{
    const float* x    = (const float*)d_in[0];
    const float* Wq   = (const float*)d_in[1];
    const float* bq   = (const float*)d_in[2];
    const float* Wk   = (const float*)d_in[3];
    const float* bk   = (const float*)d_in[4];
    const float* Wv   = (const float*)d_in[5];
    const float* bv   = (const float*)d_in[6];
    const float* Wo   = (const float*)d_in[7];
    const float* bo   = (const float*)d_in[8];
    const float* beta = (const float*)d_in[9];
    float* out = (float*)d_out;

    cudaFuncSetAttribute(gemm_mma, cudaFuncAttributeMaxDynamicSharedMemorySize,
                         SMEM_BYTES);

    convert_xw<<<K1_BLOCKS, 256>>>(x, Wq, Wk, out, bo);
    gemm_mma<<<dim3(NTOT / 128, MROWS / 128), 256, SMEM_BYTES>>>(bq, bk, beta);
    reduce_kv<<<dim3(BSZ, RCH), 256>>>(x);
    combine_mv<<<dim3(ZB, 8), 256>>>(Wk, bk, Wv, bv);
    scores<<<dim3(ZB, 4), 256>>>(x, Wq, bq, beta);
    coef_atomic<<<256, 256>>>(Wo, out);
}